// round 13
// baseline (speedup 1.0000x reference)
#include <cuda_runtime.h>
#include <math.h>

// ---------------------------------------------------------------------------
// Problem constants
// ---------------------------------------------------------------------------
#define N_TL   32768   // timeline sequences
#define T_TL   32      // timeline seq len
#define B_SZ   512     // batch
#define T_TX   64      // text seq len
#define E_DIM  50      // embedding
#define H_DIM  32      // rnn hidden

typedef unsigned long long ull;

// ---------------------------------------------------------------------------
// Scratch (static device globals; no runtime allocation allowed)
// ---------------------------------------------------------------------------
__device__ float g_h2[(size_t)N_TL * 64];   // timeline RNN final hidden [N, 2H]
__device__ float g_hn[(size_t)B_SZ * 64];   // text RNN final hidden [B, 2H]
__device__ float g_red[(size_t)B_SZ * 192]; // per-batch [mean | min | max]

// ---------------------------------------------------------------------------
// f32x2 helpers (validated R4-R12) + hardware tanh (validated R7/R12)
// ---------------------------------------------------------------------------
__device__ __forceinline__ void fma2(ull& d, ull a, ull b) {
    asm("fma.rn.f32x2 %0, %1, %2, %0;" : "+l"(d) : "l"(a), "l"(b));
}
__device__ __forceinline__ ull pack2(float lo, float hi) {
    ull r; asm("mov.b64 %0, {%1, %2};" : "=l"(r) : "f"(lo), "f"(hi)); return r;
}
__device__ __forceinline__ float red2(ull a) {
    float lo, hi;
    asm("mov.b64 {%0, %1}, %2;" : "=f"(lo), "=f"(hi) : "l"(a));
    return lo + hi;
}
__device__ __forceinline__ float tanh_hw(float x) {
    float y; asm("tanh.approx.f32 %0, %1;" : "=f"(y) : "f"(x)); return y;
}
__device__ __forceinline__ float tanh_acc(float x) {   // head-precision tanh
    x = fminf(fmaxf(x, -20.0f), 20.0f);
    float e = __expf(2.0f * x);
    return __fdividef(e - 1.0f, e + 1.0f);
}

// ===========================================================================
// FUSED RNN — warp = one sequence, both directions, two phases.
//
// Phase 1 (input projection, no recurrence):
//   For each row r, all lanes read the SAME x row via uniform-address LDG
//   (1 L1 wavefront per load — gmem broadcast is free, unlike the smem
//   crossbar). Lane (half = lane>>4, u = lane&15) computes the two outputs
//   (units u, u+16) of its direction with K-packed FFMA2 weights in regs,
//   bias folded, and stores them as ONE float2 into its LANE-PRIVATE smem
//   slot xw[r*64 + half*32 + 2u]. No syncs: each lane later reads exactly
//   the bytes it wrote (program order). Body = R9's validated xw kernel.
//
// Phase 2 (recurrence): per step only h·Wh^T:
//   1 lane-private LDS.64 (xw pair) + 8 broadcast LDS.128 (dual-parity h
//   buffer, R7-validated banking) + 32 FFMA2 + 2 MUFU.TANH.
//   Per-step crossbar demand: 34 SM-cyc (was 84 in R7/R12).
//
// Blocks of 4 warps; dynamic smem = 4*(T*64+160) floats.
// ===========================================================================
template <int T, bool TL>
__global__ __launch_bounds__(128)
void rnn_fused_kernel(const float* __restrict__ X,
                      const float* __restrict__ wif, const float* __restrict__ whf,
                      const float* __restrict__ bif, const float* __restrict__ bhf,
                      const float* __restrict__ wib, const float* __restrict__ whb,
                      const float* __restrict__ bib, const float* __restrict__ bhb)
{
    extern __shared__ __align__(16) float sh[];
    const int w    = threadIdx.x >> 5;
    const int lane = threadIdx.x & 31;
    const int half = lane >> 4;       // 0 = fwd, 1 = bwd
    const int u    = lane & 15;       // first owned unit
    const int dofs = half * 36;
    const int n    = blockIdx.x * 4 + w;

    float* xw = sh + w * (T * 64 + 160);   // [T][64] lane-private xw slots
    float* hw = xw + T * 64;               // [2 parities][72] h broadcast buf

    const float* wi = half ? wib : wif;
    const float* wh = half ? whb : whf;
    const float* bi = half ? bib : bif;
    const float* bh = half ? bhb : bhf;

    const float* xb = X + (size_t)n * (T * E_DIM);

    // ---------------- Phase 1: xw[r] = x_r · Wi^T + bias ----------------
    {
        ull WA[25], WB[25];
#pragma unroll
        for (int q = 0; q < 25; q++) {
            WA[q] = pack2(__ldg(wi + u * E_DIM + 2 * q),        __ldg(wi + u * E_DIM + 2 * q + 1));
            WB[q] = pack2(__ldg(wi + (u + 16) * E_DIM + 2 * q), __ldg(wi + (u + 16) * E_DIM + 2 * q + 1));
        }
        const float biasA = __ldg(bi + u)      + __ldg(bh + u);
        const float biasB = __ldg(bi + u + 16) + __ldg(bh + u + 16);

#pragma unroll 1
        for (int r = 0; r < T; r++) {
            const float* rp = xb + r * E_DIM;
            // uniform-address row load; 16B alignment alternates with r parity
            ull xp[25];
            if (r & 1) {
                float2 t = __ldg(reinterpret_cast<const float2*>(rp));
                xp[0] = pack2(t.x, t.y);
                const float4* p4 = reinterpret_cast<const float4*>(rp + 2);
#pragma unroll
                for (int i = 0; i < 12; i++) {
                    float4 v = __ldg(p4 + i);
                    xp[1 + 2 * i] = pack2(v.x, v.y);
                    xp[2 + 2 * i] = pack2(v.z, v.w);
                }
            } else {
                const float4* p4 = reinterpret_cast<const float4*>(rp);
#pragma unroll
                for (int i = 0; i < 12; i++) {
                    float4 v = __ldg(p4 + i);
                    xp[2 * i]     = pack2(v.x, v.y);
                    xp[2 * i + 1] = pack2(v.z, v.w);
                }
                float2 t = __ldg(reinterpret_cast<const float2*>(rp + 48));
                xp[24] = pack2(t.x, t.y);
            }

            ull aA0 = pack2(biasA, 0.0f), aA1 = 0ULL;
            ull aB0 = pack2(biasB, 0.0f), aB1 = 0ULL;
#pragma unroll
            for (int p = 0; p < 25; p++) {
                if (p & 1) { fma2(aA1, xp[p], WA[p]); fma2(aB1, xp[p], WB[p]); }
                else       { fma2(aA0, xp[p], WA[p]); fma2(aB0, xp[p], WB[p]); }
            }
            *reinterpret_cast<float2*>(xw + r * 64 + half * 32 + 2 * u) =
                make_float2(red2(aA0) + red2(aA1), red2(aB0) + red2(aB1));
        }
    }   // Wi registers die here — ptxas can reuse them for Wh

    // ---------------- Phase 2: recurrence h = tanh(xw + h·Wh^T) ---------
    ull WhA[16], WhB[16];
#pragma unroll
    for (int q = 0; q < 16; q++) {
        WhA[q] = pack2(__ldg(wh + u * H_DIM + 2 * q),        __ldg(wh + u * H_DIM + 2 * q + 1));
        WhB[q] = pack2(__ldg(wh + (u + 16) * H_DIM + 2 * q), __ldg(wh + (u + 16) * H_DIM + 2 * q + 1));
    }

    hw[dofs + u]      = 0.0f;
    hw[dofs + u + 16] = 0.0f;
    __syncwarp();

    float h0 = 0.0f, h1 = 0.0f;
#pragma unroll 1
    for (int s = 0; s < T; s++) {
        const int p  = s & 1;
        const int rt = half ? (T - 1 - s) : s;
        const float2 xv = *reinterpret_cast<const float2*>(xw + rt * 64 + half * 32 + 2 * u);

        ull aA0 = pack2(xv.x, 0.0f), aA1 = 0ULL;
        ull aB0 = pack2(xv.y, 0.0f), aB1 = 0ULL;
        const ulonglong2* hr = reinterpret_cast<const ulonglong2*>(hw + p * 72 + dofs);
#pragma unroll
        for (int q = 0; q < 8; q++) {
            ulonglong2 v = hr[q];
            fma2(aA0, v.x, WhA[2 * q]);
            fma2(aA1, v.y, WhA[2 * q + 1]);
            fma2(aB0, v.x, WhB[2 * q]);
            fma2(aB1, v.y, WhB[2 * q + 1]);
        }
        h0 = tanh_hw(red2(aA0) + red2(aA1));
        h1 = tanh_hw(red2(aB0) + red2(aB1));
        hw[(p ^ 1) * 72 + dofs + u]      = h0;
        hw[(p ^ 1) * 72 + dofs + u + 16] = h1;
        __syncwarp();
    }

    float* op = TL ? g_h2 : g_hn;
    op[(size_t)n * 64 + half * 32 + u]      = h0;
    op[(size_t)n * 64 + half * 32 + u + 16] = h1;
}

// ---------------------------------------------------------------------------
// Ragged segment mean/min/max over g_h2 (validated R2-R12)
// ---------------------------------------------------------------------------
__global__ void seg_reduce_kernel(const int* __restrict__ te)
{
    const int b = blockIdx.x;
    const int c = threadIdx.x;   // 0..63
    __shared__ int s_off;
    if (c == 0) {
        int o = 0;
        for (int i = 0; i < b; i++) o += te[i];
        s_off = o;
    }
    __syncthreads();
    const int cnt = te[b];
    const float* hp = g_h2 + (size_t)s_off * 64 + c;
    float sm = 0.0f, mn = 3.402823466e38f, mx = -3.402823466e38f;
    for (int r = 0; r < cnt; r++) {
        float v = hp[(size_t)r * 64];
        sm += v;
        mn = fminf(mn, v);
        mx = fmaxf(mx, v);
    }
    const float inv = (cnt > 0) ? __fdividef(1.0f, (float)cnt) : 0.0f;
    g_red[b * 192 + c]       = sm * inv;
    g_red[b * 192 + 64 + c]  = mn;
    g_red[b * 192 + 128 + c] = mx;
}

// ---------------------------------------------------------------------------
// Head (validated R3-R12): one block per batch row, coalesced fc1 dots.
// ---------------------------------------------------------------------------
__global__ __launch_bounds__(128)
void head_kernel(const float* __restrict__ nf,
                 const float* __restrict__ fc1_w, const float* __restrict__ fc1_b,
                 const float* __restrict__ fc2_w, const float* __restrict__ fc2_b,
                 float* __restrict__ out)
{
    __shared__ float xv[305];
    __shared__ float yp[4];
    const int row  = blockIdx.x;
    const int tid  = threadIdx.x;
    const int w    = tid >> 5;
    const int lane = tid & 31;

    for (int i = tid; i < 305; i += 128) {
        float v;
        if (i < 64)        v = g_hn[(size_t)row * 64 + i];
        else if (i < 113)  v = nf[(size_t)row * 49 + (i - 64)];
        else               v = g_red[(size_t)row * 192 + (i - 113)];
        xv[i] = v;
    }
    __syncthreads();

    float acc = 0.0f;
#pragma unroll
    for (int uu = 0; uu < 8; uu++) {
        const int u = w * 8 + uu;
        const float* wr = fc1_w + (size_t)u * 305;
        float ps = 0.0f;
        for (int k = lane; k < 305; k += 32)
            ps = fmaf(__ldg(wr + k), xv[k], ps);
#pragma unroll
        for (int o = 16; o > 0; o >>= 1) ps += __shfl_xor_sync(0xffffffffu, ps, o);
        if (lane == 0) {
            float y = tanh_acc(ps + __ldg(fc1_b + u));
            acc = fmaf(y, __ldg(fc2_w + u), acc);
        }
    }
    if (lane == 0) yp[w] = acc;
    __syncthreads();
    if (tid == 0) {
        float z = yp[0] + yp[1] + yp[2] + yp[3] + __ldg(fc2_b);
        out[row] = __fdividef(1.0f, 1.0f + __expf(-z));
    }
}

// ---------------------------------------------------------------------------
// Launch. Runtime input-ordering detection (validated R2-R12).
// Pure kernel launches + cudaFuncSetAttribute (validated R5) — capturable.
// Per-rnn input layout: wif, whf, bif, bhf, wib, whb, bib, bhb.
// ---------------------------------------------------------------------------
extern "C" void kernel_launch(void* const* d_in, const int* in_sizes, int n_in,
                              void* d_out, int out_size)
{
    int base_r1, base_r2, base_fc, idx_te;
    if (in_sizes[3] == B_SZ) {          // setup_inputs order
        idx_te = 3;  base_r1 = 4;  base_r2 = 12; base_fc = 20;
    } else {                            // reference signature order
        base_r1 = 3; base_r2 = 11; base_fc = 19; idx_te = n_in - 1;
    }

    const float* nf  = (const float*)d_in[0];
    const float* tf  = (const float*)d_in[1];
    const float* ttf = (const float*)d_in[2];
    const int*   te  = (const int*)d_in[idx_te];
#define FPTR(i) ((const float*)d_in[(i)])

    // Timeline RNN: 8192 blocks x 4 warps, warp = one sequence.
    {
        const int smem = 4 * (T_TL * 64 + 160) * sizeof(float);   // 35,328 B
        cudaFuncSetAttribute((const void*)rnn_fused_kernel<T_TL, true>,
                             cudaFuncAttributeMaxDynamicSharedMemorySize, smem);
        rnn_fused_kernel<T_TL, true><<<N_TL / 4, 128, smem>>>(
            ttf,
            FPTR(base_r2 + 0), FPTR(base_r2 + 1), FPTR(base_r2 + 2), FPTR(base_r2 + 3),
            FPTR(base_r2 + 4), FPTR(base_r2 + 5), FPTR(base_r2 + 6), FPTR(base_r2 + 7));
    }

    // Text RNN: 128 blocks x 4 warps (512 sequences, T = 64).
    {
        const int smem = 4 * (T_TX * 64 + 160) * sizeof(float);   // 68,096 B
        cudaFuncSetAttribute((const void*)rnn_fused_kernel<T_TX, false>,
                             cudaFuncAttributeMaxDynamicSharedMemorySize, smem);
        rnn_fused_kernel<T_TX, false><<<B_SZ / 4, 128, smem>>>(
            tf,
            FPTR(base_r1 + 0), FPTR(base_r1 + 1), FPTR(base_r1 + 2), FPTR(base_r1 + 3),
            FPTR(base_r1 + 4), FPTR(base_r1 + 5), FPTR(base_r1 + 6), FPTR(base_r1 + 7));
    }

    // Segment mean/min/max.
    seg_reduce_kernel<<<B_SZ, 64>>>(te);

    // Head.
    head_kernel<<<B_SZ, 128>>>(
        nf,
        FPTR(base_fc + 0), FPTR(base_fc + 1), FPTR(base_fc + 2), FPTR(base_fc + 3),
        (float*)d_out);
#undef FPTR
}